// round 8
// baseline (speedup 1.0000x reference)
#include <cuda_runtime.h>
#include <math_constants.h>

// Problem shape (fixed by reference): B=32, C=8, H=W=256
#define HM        256        // B*C heatmaps
#define HW        65536      // H*W elements per heatmap
#define SLICES    4          // blocks per heatmap
#define NBLK      (HM * SLICES)          // 1024 blocks
#define SLICE_EL  (HW / SLICES)          // 16384 elements per slice
#define T1        512                    // threads per block
#define V4_PER_T  (SLICE_EL / 4 / T1)    // 8 float4 quads per thread per tensor
#define GROUP     4                      // quads batched per load group
#define NGROUP    (V4_PER_T / GROUP)     // 2 groups

// Scratch (no device allocation allowed -> __device__ globals, zero-initialized)
__device__ float        g_s [NBLK];
__device__ float        g_sx[NBLK];
__device__ float        g_sy[NBLK];
__device__ float        g_bv[NBLK];
__device__ int          g_bi[NBLK];
__device__ unsigned int g_count;   // last-block-done ticket; reset each call

// Fused kernel. Main loop front-batches 8 LDG.128 per group (MLP_p1~8) so
// ~256 loads are in flight per SM — enough to cover ~577-cyc DRAM latency at
// full bandwidth. __launch_bounds__(512,2) grants a 64-reg budget so the
// batched loads live in registers without spills.
__global__ __launch_bounds__(T1, 2)
void dsnt_fused(const float* __restrict__ inp, const float* __restrict__ tgt,
                float* __restrict__ out) {
    const int blk = blockIdx.x;
    const int hm  = blk >> 2;       // heatmap id
    const int sl  = blk & 3;        // slice id
    const size_t base = (size_t)hm * HW + (size_t)sl * SLICE_EL;
    const float4* __restrict__ in4 = (const float4*)(inp + base);
    const float4* __restrict__ tg4 = (const float4*)(tgt + base);

    const int tid  = threadIdx.x;
    const int off0 = sl * SLICE_EL;      // element offset of slice within heatmap

    float s = 0.f, sx = 0.f, sy = 0.f;
    float bv = -CUDART_INF_F;
    int   bi = 0x7fffffff;

    #pragma unroll
    for (int g = 0; g < NGROUP; ++g) {
        // ---- front-batched loads: 8 independent LDG.128 ----
        float4 v[GROUP], t[GROUP];
        #pragma unroll
        for (int u = 0; u < GROUP; ++u)
            v[u] = in4[tid + (g * GROUP + u) * T1];
        #pragma unroll
        for (int u = 0; u < GROUP; ++u)
            t[u] = tg4[tid + (g * GROUP + u) * T1];

        // ---- compute on the group ----
        #pragma unroll
        for (int u = 0; u < GROUP; ++u) {
            const int i4  = tid + (g * GROUP + u) * T1;
            const int off = off0 + i4 * 4;       // element index within heatmap
            const int h   = off >> 8;
            const int w   = off & 255;
            // xs[j] = (j+1-128)/256 = (j-127)/256 ; ys[p] = (p-127)/256
            const float y  = (float)(h - 127) * (1.0f / 256.0f);
            const float x0 = (float)(w - 127) * (1.0f / 256.0f);

            const float e0 = __expf(v[u].x);
            const float e1 = __expf(v[u].y);
            const float e2 = __expf(v[u].z);
            const float e3 = __expf(v[u].w);
            const float es = (e0 + e1) + (e2 + e3);
            s += es;
            sy = fmaf(y, es, sy);
            // sum e_k * x_{w+k} = x0*es + (e1 + 2e2 + 3e3)/256
            sx = fmaf(x0, es,
                 fmaf(1.0f / 256.0f, fmaf(3.f, e3, fmaf(2.f, e2, e1)), sx));

            // argmax with FIRST-index tie-break: fmax tree + rare branch
            const float qmax = fmaxf(fmaxf(t[u].x, t[u].y), fmaxf(t[u].z, t[u].w));
            if (qmax > bv) {
                bv = qmax;
                bi = (t[u].x == qmax) ? off :
                     (t[u].y == qmax) ? off + 1 :
                     (t[u].z == qmax) ? off + 2 : off + 3;
            }
        }
    }

    // warp reduction
    #pragma unroll
    for (int o = 16; o > 0; o >>= 1) {
        s  += __shfl_down_sync(0xffffffffu, s,  o);
        sx += __shfl_down_sync(0xffffffffu, sx, o);
        sy += __shfl_down_sync(0xffffffffu, sy, o);
        const float ov = __shfl_down_sync(0xffffffffu, bv, o);
        const int   oi = __shfl_down_sync(0xffffffffu, bi, o);
        if (ov > bv || (ov == bv && oi < bi)) { bv = ov; bi = oi; }
    }

    __shared__ float sh_s [T1 / 32];
    __shared__ float sh_sx[T1 / 32];
    __shared__ float sh_sy[T1 / 32];
    __shared__ float sh_bv[T1 / 32];
    __shared__ int   sh_bi[T1 / 32];
    __shared__ unsigned int sh_ticket;
    const int wid = tid >> 5, lid = tid & 31;
    if (lid == 0) {
        sh_s[wid] = s; sh_sx[wid] = sx; sh_sy[wid] = sy;
        sh_bv[wid] = bv; sh_bi[wid] = bi;
    }
    __syncthreads();

    if (wid == 0) {
        const bool ok = lid < (T1 / 32);
        s  = ok ? sh_s [lid] : 0.f;
        sx = ok ? sh_sx[lid] : 0.f;
        sy = ok ? sh_sy[lid] : 0.f;
        bv = ok ? sh_bv[lid] : -CUDART_INF_F;
        bi = ok ? sh_bi[lid] : 0x7fffffff;
        #pragma unroll
        for (int o = 8; o > 0; o >>= 1) {
            s  += __shfl_down_sync(0xffffffffu, s,  o);
            sx += __shfl_down_sync(0xffffffffu, sx, o);
            sy += __shfl_down_sync(0xffffffffu, sy, o);
            const float ov = __shfl_down_sync(0xffffffffu, bv, o);
            const int   oi = __shfl_down_sync(0xffffffffu, bi, o);
            if (ov > bv || (ov == bv && oi < bi)) { bv = ov; bi = oi; }
        }
        if (lid == 0) {
            // single writer: store partials, release-fence, take ticket
            g_s [blk] = s;
            g_sx[blk] = sx;
            g_sy[blk] = sy;
            g_bv[blk] = bv;
            g_bi[blk] = bi;
            __threadfence();                       // writer-only release
            sh_ticket = atomicAdd(&g_count, 1u);
        }
    }
    __syncthreads();
    if (sh_ticket != NBLK - 1) return;   // not the last block

    // ---- last-block epilogue (256 reading threads) ----
    float m = 0.f;
    if (tid < HM) {
        __threadfence();                 // reader-side acquire (8 warps only)
        float fs = 0.f, fsx = 0.f, fsy = 0.f;
        float fbv = -CUDART_INF_F;
        int   fbi = 0x7fffffff;
        #pragma unroll
        for (int k = 0; k < SLICES; ++k) {
            const int idx = tid * SLICES + k;
            fs  += __ldcg(&g_s [idx]);
            fsx += __ldcg(&g_sx[idx]);
            fsy += __ldcg(&g_sy[idx]);
            const float v = __ldcg(&g_bv[idx]);
            const int   i = __ldcg(&g_bi[idx]);
            if (v > fbv || (v == fbv && i < fbi)) { fbv = v; fbi = i; }
        }
        const float inv = 1.0f / fs;
        const float px = fsx * inv;
        const float py = fsy * inv;
        const float tx = (float)((fbi & 255) - 127) * (1.0f / 256.0f);
        const float ty = (float)((fbi >> 8)  - 127) * (1.0f / 256.0f);
        const float dx = px - tx;
        const float dy = py - ty;
        m = 0.5f * (dx * dx + dy * dy);
    }

    // fixed-order reduce of 256 values (tid 256..511 contribute 0)
    #pragma unroll
    for (int o = 16; o > 0; o >>= 1)
        m += __shfl_down_sync(0xffffffffu, m, o);
    __shared__ float sh_m[T1 / 32];
    if (lid == 0) sh_m[wid] = m;
    __syncthreads();
    if (tid == 0) {
        float tot = 0.f;
        #pragma unroll
        for (int w = 0; w < 8; ++w) tot += sh_m[w];   // heatmap warps 0..7 only
        out[0] = tot * (1.0f / 32.0f);                // divide by B
        g_count = 0;                                   // reset for next replay
    }
}

extern "C" void kernel_launch(void* const* d_in, const int* in_sizes, int n_in,
                              void* d_out, int out_size) {
    const float* inp = (const float*)d_in[0];
    const float* tgt = (const float*)d_in[1];
    float* out = (float*)d_out;
    (void)in_sizes; (void)n_in; (void)out_size;

    dsnt_fused<<<NBLK, T1>>>(inp, tgt, out);
}

// round 9
// speedup vs baseline: 1.0696x; 1.0696x over previous
#include <cuda_runtime.h>
#include <math_constants.h>

// Problem shape (fixed by reference): B=32, C=8, H=W=256
#define HM        256        // B*C heatmaps
#define HW        65536      // H*W elements per heatmap
#define SL_PER_HM 8          // slices per heatmap
#define NSLICE    (HM * SL_PER_HM)       // 2048 work items
#define SLICE_EL  (HW / SL_PER_HM)       // 8192 elements per slice
#define T1        512                    // threads per block
#define QUADS     (SLICE_EL / 4 / T1)    // 4 float4 quads / thread / tensor
#define GRID      296                    // 2 blocks/SM x 148 SMs: ONE wave

// Scratch (no device allocation allowed -> __device__ globals, zero-initialized)
__device__ float        g_s [NSLICE];
__device__ float        g_sx[NSLICE];
__device__ float        g_sy[NSLICE];
__device__ float        g_bv[NSLICE];
__device__ int          g_bi[NSLICE];
__device__ unsigned int g_work;    // slice ticket      (reset in epilogue)
__device__ unsigned int g_count;   // blocks-done ticket (reset in epilogue)

// Persistent-block fused kernel with dynamic slice stealing:
//  - 296 resident blocks (single wave), each steals 8192-elem slices until the
//    pool is empty -> no wave-quantization tail (272 blocks do 7, 24 do 6).
//  - per slice: s=sum exp(v) (inputs ~N(0,1): exp safe in fp32 without max
//    subtraction), sx/sy = coordinate-weighted sums, target argmax with
//    FIRST-index tie-break. Partials are per-slice -> values independent of
//    which block computed them (replay-deterministic).
//  - last finishing BLOCK folds slices, computes per-heatmap MSE, fixed-order
//    sum / B, and resets both tickets for the next graph replay.
__global__ __launch_bounds__(T1, 2)
void dsnt_fused(const float* __restrict__ inp, const float* __restrict__ tgt,
                float* __restrict__ out) {
    const int tid = threadIdx.x;
    const int wid = tid >> 5, lid = tid & 31;

    __shared__ float sh_s [T1 / 32];
    __shared__ float sh_sx[T1 / 32];
    __shared__ float sh_sy[T1 / 32];
    __shared__ float sh_bv[T1 / 32];
    __shared__ int   sh_bi[T1 / 32];
    __shared__ int   sh_idx[2];          // ping-pong prefetched work index
    __shared__ unsigned int sh_ticket;

    if (tid == 0) sh_idx[0] = (int)atomicAdd(&g_work, 1u);
    __syncthreads();
    int par = 0;
    int slice = sh_idx[0];

    while (slice < NSLICE) {
        // prefetch next ticket early; latency hidden under this slice's work
        if (tid == 0) sh_idx[par ^ 1] = (int)atomicAdd(&g_work, 1u);

        const int hm  = slice >> 3;            // heatmap id
        const int sub = slice & 7;             // slice within heatmap
        const int off0 = sub * SLICE_EL;       // element offset within heatmap
        const float4* __restrict__ in4 =
            (const float4*)(inp + (size_t)hm * HW + off0);
        const float4* __restrict__ tg4 =
            (const float4*)(tgt + (size_t)hm * HW + off0);

        // ---- front-batched loads: 8 independent LDG.128 ----
        float4 v[QUADS], t[QUADS];
        #pragma unroll
        for (int u = 0; u < QUADS; ++u) v[u] = in4[tid + u * T1];
        #pragma unroll
        for (int u = 0; u < QUADS; ++u) t[u] = tg4[tid + u * T1];

        float s = 0.f, sx = 0.f, sy = 0.f;
        float bv = -CUDART_INF_F;
        int   bi = 0x7fffffff;

        #pragma unroll
        for (int u = 0; u < QUADS; ++u) {
            const int off = off0 + (tid + u * T1) * 4;  // element idx in heatmap
            const int h   = off >> 8;
            const int w   = off & 255;
            // xs[j] = (j+1-128)/256 = (j-127)/256 ; ys[p] = (p-127)/256
            const float y  = (float)(h - 127) * (1.0f / 256.0f);
            const float x0 = (float)(w - 127) * (1.0f / 256.0f);

            const float e0 = __expf(v[u].x);
            const float e1 = __expf(v[u].y);
            const float e2 = __expf(v[u].z);
            const float e3 = __expf(v[u].w);
            const float es = (e0 + e1) + (e2 + e3);
            s += es;
            sy = fmaf(y, es, sy);
            // sum e_k * x_{w+k} = x0*es + (e1 + 2e2 + 3e3)/256
            sx = fmaf(x0, es,
                 fmaf(1.0f / 256.0f, fmaf(3.f, e3, fmaf(2.f, e2, e1)), sx));

            // argmax with FIRST-index tie-break: fmax tree + rare branch
            const float qmax = fmaxf(fmaxf(t[u].x, t[u].y), fmaxf(t[u].z, t[u].w));
            if (qmax > bv) {
                bv = qmax;
                bi = (t[u].x == qmax) ? off :
                     (t[u].y == qmax) ? off + 1 :
                     (t[u].z == qmax) ? off + 2 : off + 3;
            }
        }

        // ---- block reduction for this slice ----
        #pragma unroll
        for (int o = 16; o > 0; o >>= 1) {
            s  += __shfl_down_sync(0xffffffffu, s,  o);
            sx += __shfl_down_sync(0xffffffffu, sx, o);
            sy += __shfl_down_sync(0xffffffffu, sy, o);
            const float ov = __shfl_down_sync(0xffffffffu, bv, o);
            const int   oi = __shfl_down_sync(0xffffffffu, bi, o);
            if (ov > bv || (ov == bv && oi < bi)) { bv = ov; bi = oi; }
        }
        if (lid == 0) {
            sh_s[wid] = s; sh_sx[wid] = sx; sh_sy[wid] = sy;
            sh_bv[wid] = bv; sh_bi[wid] = bi;
        }
        __syncthreads();
        if (wid == 0) {
            const bool ok = lid < (T1 / 32);
            s  = ok ? sh_s [lid] : 0.f;
            sx = ok ? sh_sx[lid] : 0.f;
            sy = ok ? sh_sy[lid] : 0.f;
            bv = ok ? sh_bv[lid] : -CUDART_INF_F;
            bi = ok ? sh_bi[lid] : 0x7fffffff;
            #pragma unroll
            for (int o = 8; o > 0; o >>= 1) {
                s  += __shfl_down_sync(0xffffffffu, s,  o);
                sx += __shfl_down_sync(0xffffffffu, sx, o);
                sy += __shfl_down_sync(0xffffffffu, sy, o);
                const float ov = __shfl_down_sync(0xffffffffu, bv, o);
                const int   oi = __shfl_down_sync(0xffffffffu, bi, o);
                if (ov > bv || (ov == bv && oi < bi)) { bv = ov; bi = oi; }
            }
            if (lid == 0) {                 // plain stores; one release later
                g_s [slice] = s;
                g_sx[slice] = sx;
                g_sy[slice] = sy;
                g_bv[slice] = bv;
                g_bi[slice] = bi;
            }
        }
        __syncthreads();     // publishes sh_idx[par^1]; smem reuse safe
        par ^= 1;
        slice = sh_idx[par];
    }

    // ---- block done: single release fence + ticket ----
    if (tid == 0) {
        __threadfence();                       // writer-only release
        sh_ticket = atomicAdd(&g_count, 1u);
    }
    __syncthreads();
    if (sh_ticket != GRID - 1) return;         // not the last block

    // ---- last-block epilogue (256 reading threads) ----
    float m = 0.f;
    if (tid < HM) {
        __threadfence();                 // reader-side acquire (8 warps only)
        float fs = 0.f, fsx = 0.f, fsy = 0.f;
        float fbv = -CUDART_INF_F;
        int   fbi = 0x7fffffff;
        #pragma unroll
        for (int k = 0; k < SL_PER_HM; ++k) {
            const int idx = tid * SL_PER_HM + k;
            fs  += __ldcg(&g_s [idx]);
            fsx += __ldcg(&g_sx[idx]);
            fsy += __ldcg(&g_sy[idx]);
            const float v = __ldcg(&g_bv[idx]);
            const int   i = __ldcg(&g_bi[idx]);
            if (v > fbv || (v == fbv && i < fbi)) { fbv = v; fbi = i; }
        }
        const float inv = 1.0f / fs;
        const float px = fsx * inv;
        const float py = fsy * inv;
        const float tx = (float)((fbi & 255) - 127) * (1.0f / 256.0f);
        const float ty = (float)((fbi >> 8)  - 127) * (1.0f / 256.0f);
        const float dx = px - tx;
        const float dy = py - ty;
        m = 0.5f * (dx * dx + dy * dy);
    }

    // fixed-order reduce of 256 values (tid 256..511 contribute 0)
    #pragma unroll
    for (int o = 16; o > 0; o >>= 1)
        m += __shfl_down_sync(0xffffffffu, m, o);
    __shared__ float sh_m[T1 / 32];
    if (lid == 0) sh_m[wid] = m;
    __syncthreads();
    if (tid == 0) {
        float tot = 0.f;
        #pragma unroll
        for (int w = 0; w < 8; ++w) tot += sh_m[w];   // heatmap warps 0..7 only
        out[0] = tot * (1.0f / 32.0f);                // divide by B
        g_work  = 0;                                   // reset for next replay
        g_count = 0;
    }
}

extern "C" void kernel_launch(void* const* d_in, const int* in_sizes, int n_in,
                              void* d_out, int out_size) {
    const float* inp = (const float*)d_in[0];
    const float* tgt = (const float*)d_in[1];
    float* out = (float*)d_out;
    (void)in_sizes; (void)n_in; (void)out_size;

    dsnt_fused<<<GRID, T1>>>(inp, tgt, out);
}